// round 8
// baseline (speedup 1.0000x reference)
#include <cuda_runtime.h>
#include <cuda_bf16.h>

// RWKV single-token inference, fp32 — persistent kernel, 148x512,
// grid barrier between phases, warp-pair row split for high MLP.
// D=1024, H=4096, L=24, V=50277.

#define D    1024
#define HD   4096
#define NL   24
#define NV   50277
#define GRID 148
#define NTH  512
#define NWARP 16
#define TOTW (GRID * NWARP)   // 2368 warps
#define TOTP (GRID * 8)       // 1184 warp-pairs

__device__ __align__(16) float g_x[D];
__device__ __align__(16) float g_rwkv[D];
__device__ __align__(16) float g_kk[HD];
__device__ __align__(16) float g_r2[D];
__device__ __align__(16) float g_state_scratch[NL * 5 * D];
__device__ unsigned g_count;
__device__ unsigned g_gen;

__device__ __forceinline__ float warp_sum(float s) {
#pragma unroll
    for (int o = 16; o > 0; o >>= 1) s += __shfl_xor_sync(0xffffffffu, s, o);
    return s;
}

__device__ __forceinline__ float block_sum512(float v, float* sred) {
    __syncthreads();
    v = warp_sum(v);
    int warp = threadIdx.x >> 5, lane = threadIdx.x & 31;
    if (lane == 0) sred[warp] = v;
    __syncthreads();
    float t = 0.f;
#pragma unroll
    for (int w = 0; w < NWARP; w++) t += sred[w];
    return t;
}

// Grid barrier: all 148 blocks co-resident (1 CTA/SM).
__device__ __forceinline__ void grid_barrier() {
    __syncthreads();
    if (threadIdx.x == 0) {
        __threadfence();
        volatile unsigned* genp = &g_gen;
        unsigned gen = *genp;
        if (atomicAdd(&g_count, 1u) == GRID - 1) {
            atomicExch(&g_count, 0u);
            __threadfence();
            atomicExch(&g_gen, gen + 1u);
        } else {
            while (*genp == gen) { __nanosleep(32); }
            __threadfence();
        }
    }
    __syncthreads();
}

#define PAIR_BAR(pl) asm volatile("bar.sync %0, %1;" :: "r"(1 + (pl)), "r"(64) : "memory")

__global__ __launch_bounds__(NTH, 1) void rwkv_fused(
    const int* __restrict__ token, const float* __restrict__ state,
    const float* __restrict__ emb,
    const float* __restrict__ ln0_w, const float* __restrict__ ln0_b,
    const float* __restrict__ ln1_w, const float* __restrict__ ln1_b,
    const float* __restrict__ ln2_w, const float* __restrict__ ln2_b,
    const float* __restrict__ kw, const float* __restrict__ vw,
    const float* __restrict__ rw, const float* __restrict__ ow,
    const float* __restrict__ mk, const float* __restrict__ mv,
    const float* __restrict__ mr,
    const float* __restrict__ tf, const float* __restrict__ td,
    const float* __restrict__ fkw, const float* __restrict__ fvw,
    const float* __restrict__ frw,
    const float* __restrict__ fmk, const float* __restrict__ fmr,
    const float* __restrict__ lnw, const float* __restrict__ lnb,
    const float* __restrict__ head,
    float* __restrict__ logits, float* __restrict__ state_out) {
    __shared__ float sred[NWARP];
    __shared__ float s_part[NWARP * 3];
    __shared__ float s_buf[HD];   // 16KB, reused per phase

    const int t = threadIdx.x, warp = t >> 5, lane = t & 31, bid = blockIdx.x;
    const int wg = bid * NWARP + warp;          // 0..2367
    const int pl = warp >> 1;                   // pair-local 0..7
    const int pr = bid * 8 + pl;                // pair id 0..1183
    const int h = warp & 1;                     // half within pair
    const bool rowact = (pr < D);               // pair owns row pr of a DxD matvec

    // ---- embed: block 0 computes g_x = LN0(emb[token]) ----
    if (bid == 0) {
        float2 xv = ((const float2*)(emb + (size_t)token[0] * D))[t];
        float mu = block_sum512(xv.x + xv.y, sred) * (1.f / D);
        float d0 = xv.x - mu, d1 = xv.y - mu;
        float var = block_sum512(d0 * d0 + d1 * d1, sred) * (1.f / D);
        float rstd = rsqrtf(var + 1e-5f);
        float2 wv = ((const float2*)ln0_w)[t];
        float2 bv = ((const float2*)ln0_b)[t];
        float2 o;
        o.x = d0 * rstd * wv.x + bv.x;
        o.y = d1 * rstd * wv.y + bv.y;
        ((float2*)g_x)[t] = o;
    }

    for (int l = 0; l < NL; l++) {
        const size_t lo = (size_t)l * D;
        const size_t sb = (size_t)l * 5 * D;

        // ================= Phase A: time mixing =================
        // Pre-issue k-half loads before the barrier (independent of g_x).
        float4 ak[4];
        if (rowact) {
            const float4* kr = (const float4*)(kw + lo * D + (size_t)pr * D + (size_t)h * 512);
#pragma unroll
            for (int j = 0; j < 4; j++) ak[j] = kr[lane + 32 * j];
        }
        grid_barrier();   // g_x final
        {
            // issue v/r halves + epilogue scalars early
            float4 av[4], ar[4];
            float aa = 0.f, bb = 0.f, ppv = 0.f, tfv = 0.f, tdv = 0.f;
            if (rowact) {
                const float4* vr = (const float4*)(vw + lo * D + (size_t)pr * D + (size_t)h * 512);
                const float4* rr = (const float4*)(rw + lo * D + (size_t)pr * D + (size_t)h * 512);
#pragma unroll
                for (int j = 0; j < 4; j++) av[j] = vr[lane + 32 * j];
#pragma unroll
                for (int j = 0; j < 4; j++) ar[j] = rr[lane + 32 * j];
                if (h == 0 && lane == 0) {
                    aa  = state[sb + 2 * D + pr];
                    bb  = state[sb + 3 * D + pr];
                    ppv = state[sb + 4 * D + pr];
                    tfv = tf[lo + pr];
                    tdv = td[lo + pr];
                }
            }

            // LN1 + mixing into shared (xk | xv | xr)
            float2 xv2 = __ldcg((const float2*)g_x + t);
            float mu = block_sum512(xv2.x + xv2.y, sred) * (1.f / D);
            float d0 = xv2.x - mu, d1 = xv2.y - mu;
            float var = block_sum512(d0 * d0 + d1 * d1, sred) * (1.f / D);
            float rstd = rsqrtf(var + 1e-5f);
            float2 w1 = ((const float2*)(ln1_w + lo))[t];
            float2 b1 = ((const float2*)(ln1_b + lo))[t];
            float2 mk2 = ((const float2*)(mk + lo))[t];
            float2 mv2 = ((const float2*)(mv + lo))[t];
            float2 mr2 = ((const float2*)(mr + lo))[t];
            float2 sx2 = ((const float2*)(state + sb + D))[t];   // sx_att
            float xn0 = d0 * rstd * w1.x + b1.x;
            float xn1 = d1 * rstd * w1.y + b1.y;
            s_buf[2 * t]             = xn0 * mk2.x + sx2.x * (1.f - mk2.x);
            s_buf[2 * t + 1]         = xn1 * mk2.y + sx2.y * (1.f - mk2.y);
            s_buf[D + 2 * t]         = xn0 * mv2.x + sx2.x * (1.f - mv2.x);
            s_buf[D + 2 * t + 1]     = xn1 * mv2.y + sx2.y * (1.f - mv2.y);
            s_buf[2 * D + 2 * t]     = xn0 * mr2.x + sx2.x * (1.f - mr2.x);
            s_buf[2 * D + 2 * t + 1] = xn1 * mr2.y + sx2.y * (1.f - mr2.y);
            if (bid == 0) {                          // state row 1 = xn
                state_out[sb + D + 2 * t]     = xn0;
                state_out[sb + D + 2 * t + 1] = xn1;
            }
            __syncthreads();

            if (rowact) {
                const float4* xk4 = (const float4*)(s_buf) + h * 128;
                const float4* xv4 = (const float4*)(s_buf + D) + h * 128;
                const float4* xr4 = (const float4*)(s_buf + 2 * D) + h * 128;
                float sk = 0.f, sv = 0.f, sr = 0.f;
#pragma unroll
                for (int j = 0; j < 4; j++) {
                    float4 b = xk4[lane + 32 * j];
                    sk = fmaf(ak[j].x, b.x, sk); sk = fmaf(ak[j].y, b.y, sk);
                    sk = fmaf(ak[j].z, b.z, sk); sk = fmaf(ak[j].w, b.w, sk);
                    float4 c = xv4[lane + 32 * j];
                    sv = fmaf(av[j].x, c.x, sv); sv = fmaf(av[j].y, c.y, sv);
                    sv = fmaf(av[j].z, c.z, sv); sv = fmaf(av[j].w, c.w, sv);
                    float4 e = xr4[lane + 32 * j];
                    sr = fmaf(ar[j].x, e.x, sr); sr = fmaf(ar[j].y, e.y, sr);
                    sr = fmaf(ar[j].z, e.z, sr); sr = fmaf(ar[j].w, e.w, sr);
                }
                sk = warp_sum(sk); sv = warp_sum(sv); sr = warp_sum(sr);
                if (lane == 0) {
                    s_part[warp * 3]     = sk;
                    s_part[warp * 3 + 1] = sv;
                    s_part[warp * 3 + 2] = sr;
                }
                PAIR_BAR(pl);
                if (h == 0 && lane == 0) {
                    float k  = s_part[warp * 3]     + s_part[(warp + 1) * 3];
                    float v  = s_part[warp * 3 + 1] + s_part[(warp + 1) * 3 + 1];
                    float sr2 = s_part[warp * 3 + 2] + s_part[(warp + 1) * 3 + 2];
                    float rs = 1.f / (1.f + expf(-sr2));

                    float ww = tfv + k;
                    float qq = fmaxf(ppv, ww);
                    float e1 = expf(ppv - qq);
                    float e2 = expf(ww - qq);
                    g_rwkv[pr] = rs * (e1 * aa + e2 * v) / (e1 * bb + e2);

                    float ww2 = ppv + tdv;
                    float qq2 = fmaxf(ww2, k);
                    float e1b = expf(ww2 - qq2);
                    float e2b = expf(k - qq2);
                    state_out[sb + 2 * D + pr] = e1b * aa + e2b * v;
                    state_out[sb + 3 * D + pr] = e1b * bb + e2b;
                    state_out[sb + 4 * D + pr] = qq2;
                }
            }
        }

        // ================= Phase B: x += ow @ rwkv =================
        float4 bo[4];
        if (rowact) {
            const float4* orow = (const float4*)(ow + lo * D + (size_t)pr * D + (size_t)h * 512);
#pragma unroll
            for (int j = 0; j < 4; j++) bo[j] = orow[lane + 32 * j];
        }
        grid_barrier();   // g_rwkv complete
        {
            if (t < 256) ((float4*)s_buf)[t] = __ldcg((const float4*)g_rwkv + t);
            __syncthreads();
            if (rowact) {
                const float4* v4 = (const float4*)s_buf + h * 128;
                float s = 0.f;
#pragma unroll
                for (int j = 0; j < 4; j++) {
                    float4 b = v4[lane + 32 * j];
                    s = fmaf(bo[j].x, b.x, s); s = fmaf(bo[j].y, b.y, s);
                    s = fmaf(bo[j].z, b.z, s); s = fmaf(bo[j].w, b.w, s);
                }
                s = warp_sum(s);
                if (lane == 0) s_part[warp * 3] = s;
                PAIR_BAR(pl);
                if (h == 0 && lane == 0) {
                    float tot = s_part[warp * 3] + s_part[(warp + 1) * 3];
                    g_x[pr] = __ldcg(g_x + pr) + tot;
                }
            }
        }

        // ================= Phase C: channel mix 1 =================
        float4 c0[8];
        {   // first unit u0 = wg < 2368 < HD: always an fkw row
            const float4* wr0 = (const float4*)(fkw + (size_t)l * HD * D + (size_t)wg * D);
#pragma unroll
            for (int j = 0; j < 8; j++) c0[j] = wr0[lane + 32 * j];
        }
        grid_barrier();   // g_x updated
        {
            float2 xv2 = __ldcg((const float2*)g_x + t);
            float mu = block_sum512(xv2.x + xv2.y, sred) * (1.f / D);
            float d0 = xv2.x - mu, d1 = xv2.y - mu;
            float var = block_sum512(d0 * d0 + d1 * d1, sred) * (1.f / D);
            float rstd = rsqrtf(var + 1e-5f);
            float2 w2 = ((const float2*)(ln2_w + lo))[t];
            float2 b2 = ((const float2*)(ln2_b + lo))[t];
            float2 mk2 = ((const float2*)(fmk + lo))[t];
            float2 mr2 = ((const float2*)(fmr + lo))[t];
            float2 sx2 = ((const float2*)(state + sb))[t];   // sx_ffn
            float xn0 = d0 * rstd * w2.x + b2.x;
            float xn1 = d1 * rstd * w2.y + b2.y;
            s_buf[2 * t]         = xn0 * mk2.x + sx2.x * (1.f - mk2.x);
            s_buf[2 * t + 1]     = xn1 * mk2.y + sx2.y * (1.f - mk2.y);
            s_buf[D + 2 * t]     = xn0 * mr2.x + sx2.x * (1.f - mr2.x);
            s_buf[D + 2 * t + 1] = xn1 * mr2.y + sx2.y * (1.f - mr2.y);
            if (bid == 0) {                      // state row 0 = xn2
                state_out[sb + 2 * t]     = xn0;
                state_out[sb + 2 * t + 1] = xn1;
            }
            __syncthreads();

            const float4* xk4 = (const float4*)s_buf;
            const float4* xr4 = (const float4*)(s_buf + D);
            // peeled first unit
            {
                float s = 0.f;
#pragma unroll
                for (int j = 0; j < 8; j++) {
                    float4 b = xk4[lane + 32 * j];
                    s = fmaf(c0[j].x, b.x, s); s = fmaf(c0[j].y, b.y, s);
                    s = fmaf(c0[j].z, b.z, s); s = fmaf(c0[j].w, b.w, s);
                }
                s = warp_sum(s);
                if (lane == 0) { float rl = fmaxf(s, 0.f); g_kk[wg] = rl * rl; }
            }
            for (int u = wg + TOTW; u < HD + D; u += TOTW) {
                const float4* wr = (u < HD)
                    ? (const float4*)(fkw + (size_t)l * HD * D + (size_t)u * D)
                    : (const float4*)(frw + lo * D + (size_t)(u - HD) * D);
                const float4* x4 = (u < HD) ? xk4 : xr4;
                float4 a[8];
#pragma unroll
                for (int j = 0; j < 8; j++) a[j] = wr[lane + 32 * j];
                float s = 0.f;
#pragma unroll
                for (int j = 0; j < 8; j++) {
                    float4 b = x4[lane + 32 * j];
                    s = fmaf(a[j].x, b.x, s); s = fmaf(a[j].y, b.y, s);
                    s = fmaf(a[j].z, b.z, s); s = fmaf(a[j].w, b.w, s);
                }
                s = warp_sum(s);
                if (lane == 0) {
                    if (u < HD) { float rl = fmaxf(s, 0.f); g_kk[u] = rl * rl; }
                    else g_r2[u - HD] = 1.f / (1.f + expf(-s));
                }
            }
        }

        // ================= Phase D: x += r2 * (fvw @ kk) =================
        float4 d0r[8];
        if (rowact) {
            const float4* w4 = (const float4*)(fvw + (size_t)l * D * HD + (size_t)pr * HD
                                               + (size_t)h * 2048);
#pragma unroll
            for (int j = 0; j < 8; j++) d0r[j] = w4[lane + 32 * j];
        }
        grid_barrier();   // g_kk, g_r2 complete
        {
            ((float4*)s_buf)[t]       = __ldcg((const float4*)g_kk + t);
            ((float4*)s_buf)[t + NTH] = __ldcg((const float4*)g_kk + t + NTH);
            __syncthreads();
            if (rowact) {
                const float4* k4 = (const float4*)s_buf + h * 512;
                float s = 0.f;
#pragma unroll
                for (int j = 0; j < 8; j++) {
                    float4 b = k4[lane + 32 * j];
                    s = fmaf(d0r[j].x, b.x, s); s = fmaf(d0r[j].y, b.y, s);
                    s = fmaf(d0r[j].z, b.z, s); s = fmaf(d0r[j].w, b.w, s);
                }
                const float4* w4 = (const float4*)(fvw + (size_t)l * D * HD + (size_t)pr * HD
                                                   + (size_t)h * 2048);
                float4 a[8];
#pragma unroll
                for (int j = 0; j < 8; j++) a[j] = w4[256 + lane + 32 * j];
#pragma unroll
                for (int j = 0; j < 8; j++) {
                    float4 b = k4[256 + lane + 32 * j];
                    s = fmaf(a[j].x, b.x, s); s = fmaf(a[j].y, b.y, s);
                    s = fmaf(a[j].z, b.z, s); s = fmaf(a[j].w, b.w, s);
                }
                s = warp_sum(s);
                if (lane == 0) s_part[warp * 3] = s;
                PAIR_BAR(pl);
                if (h == 0 && lane == 0) {
                    float tot = s_part[warp * 3] + s_part[(warp + 1) * 3];
                    g_x[pr] = __ldcg(g_x + pr) + __ldcg(g_r2 + pr) * tot;
                }
            }
        }
    }

    // ================= Head: logits = head @ LN(x) =================
    float4 h0[8];
    {
        const float4* hr = (const float4*)(head + (size_t)wg * D);   // wg < NV
#pragma unroll
        for (int j = 0; j < 8; j++) h0[j] = hr[lane + 32 * j];
    }
    grid_barrier();   // g_x final
    {
        float2 xv2 = __ldcg((const float2*)g_x + t);
        float mu = block_sum512(xv2.x + xv2.y, sred) * (1.f / D);
        float d0 = xv2.x - mu, d1 = xv2.y - mu;
        float var = block_sum512(d0 * d0 + d1 * d1, sred) * (1.f / D);
        float rstd = rsqrtf(var + 1e-5f);
        float2 wv = ((const float2*)lnw)[t];
        float2 bv = ((const float2*)lnb)[t];
        s_buf[2 * t]     = d0 * rstd * wv.x + bv.x;
        s_buf[2 * t + 1] = d1 * rstd * wv.y + bv.y;
        __syncthreads();

        const float4* x4 = (const float4*)s_buf;
        // peeled first row
        {
            float s = 0.f;
#pragma unroll
            for (int j = 0; j < 8; j++) {
                float4 b = x4[lane + 32 * j];
                s = fmaf(h0[j].x, b.x, s); s = fmaf(h0[j].y, b.y, s);
                s = fmaf(h0[j].z, b.z, s); s = fmaf(h0[j].w, b.w, s);
            }
            s = warp_sum(s);
            if (lane == 0) logits[wg] = s;
        }
        // two rows per iteration
        for (int v = wg + TOTW; v < NV; v += 2 * TOTW) {
            int v2 = v + TOTW;
            if (v2 < NV) {
                const float4* r0 = (const float4*)(head + (size_t)v * D);
                const float4* r1 = (const float4*)(head + (size_t)v2 * D);
                float4 a0[8], a1[8];
#pragma unroll
                for (int j = 0; j < 8; j++) { a0[j] = r0[lane + 32 * j]; a1[j] = r1[lane + 32 * j]; }
                float s0 = 0.f, s1 = 0.f;
#pragma unroll
                for (int j = 0; j < 8; j++) {
                    float4 b = x4[lane + 32 * j];
                    s0 = fmaf(a0[j].x, b.x, s0); s0 = fmaf(a0[j].y, b.y, s0);
                    s0 = fmaf(a0[j].z, b.z, s0); s0 = fmaf(a0[j].w, b.w, s0);
                    s1 = fmaf(a1[j].x, b.x, s1); s1 = fmaf(a1[j].y, b.y, s1);
                    s1 = fmaf(a1[j].z, b.z, s1); s1 = fmaf(a1[j].w, b.w, s1);
                }
                s0 = warp_sum(s0); s1 = warp_sum(s1);
                if (lane == 0) { logits[v] = s0; logits[v2] = s1; }
            } else {
                const float4* r0 = (const float4*)(head + (size_t)v * D);
                float s0 = 0.f;
#pragma unroll
                for (int j = 0; j < 8; j++) {
                    float4 a = r0[lane + 32 * j];
                    float4 b = x4[lane + 32 * j];
                    s0 = fmaf(a.x, b.x, s0); s0 = fmaf(a.y, b.y, s0);
                    s0 = fmaf(a.z, b.z, s0); s0 = fmaf(a.w, b.w, s0);
                }
                s0 = warp_sum(s0);
                if (lane == 0) logits[v] = s0;
            }
        }
    }
}

// ---------------------------------------------------------------------------
extern "C" void kernel_launch(void* const* d_in, const int* in_sizes, int n_in,
                              void* d_out, int out_size) {
    const int*   token     = (const int*)d_in[0];
    const float* state     = (const float*)d_in[1];
    const float* emb       = (const float*)d_in[2];
    const float* ln0_w     = (const float*)d_in[3];
    const float* ln0_b     = (const float*)d_in[4];
    const float* ln1_w     = (const float*)d_in[5];
    const float* ln1_b     = (const float*)d_in[6];
    const float* ln2_w     = (const float*)d_in[7];
    const float* ln2_b     = (const float*)d_in[8];
    const float* att_key   = (const float*)d_in[9];
    const float* att_value = (const float*)d_in[10];
    const float* att_recep = (const float*)d_in[11];
    const float* att_out   = (const float*)d_in[12];
    const float* tm_k      = (const float*)d_in[13];
    const float* tm_v      = (const float*)d_in[14];
    const float* tm_r      = (const float*)d_in[15];
    const float* t_first   = (const float*)d_in[16];
    const float* t_decay   = (const float*)d_in[17];
    const float* ffn_key   = (const float*)d_in[18];
    const float* ffn_value = (const float*)d_in[19];
    const float* ffn_recep = (const float*)d_in[20];
    const float* ffn_tm_k  = (const float*)d_in[21];
    const float* ffn_tm_r  = (const float*)d_in[22];
    const float* lnout_w   = (const float*)d_in[23];
    const float* lnout_b   = (const float*)d_in[24];
    const float* head      = (const float*)d_in[25];

    float* out = (float*)d_out;
    float* logits = out;
    float* state_out;
    if (out_size >= NV + NL * 5 * D) {
        state_out = out + NV;
    } else {
        void* p = nullptr;
        cudaGetSymbolAddress(&p, g_state_scratch);
        state_out = (float*)p;
    }

    rwkv_fused<<<GRID, NTH>>>(token, state, emb, ln0_w, ln0_b,
                              ln1_w, ln1_b, ln2_w, ln2_b,
                              att_key, att_value, att_recep, att_out,
                              tm_k, tm_v, tm_r, t_first, t_decay,
                              ffn_key, ffn_value, ffn_recep,
                              ffn_tm_k, ffn_tm_r,
                              lnout_w, lnout_b, head,
                              logits, state_out);
}

// round 9
// speedup vs baseline: 1.1851x; 1.1851x over previous
#include <cuda_runtime.h>
#include <cuda_bf16.h>

// RWKV single-token inference, fp32 — persistent kernel (148x256), grid
// barrier between phases. R9: L2 prefetch of upcoming weight rows issued
// before each barrier + 2-row batching in the long streaming loops.
// D=1024, H=4096, L=24, V=50277.

#define D    1024
#define HD   4096
#define NL   24
#define NV   50277
#define GRID 148
#define NTH  256
#define NWARP 8
#define TOTW (GRID * NWARP)   // 1184 warps

__device__ __align__(16) float g_x[D];
__device__ __align__(16) float g_rwkv[D];
__device__ __align__(16) float g_kk[HD];
__device__ __align__(16) float g_r2[D];
__device__ __align__(16) float g_state_scratch[NL * 5 * D];
__device__ unsigned g_count;
__device__ unsigned g_gen;

__device__ __forceinline__ float warp_sum(float s) {
#pragma unroll
    for (int o = 16; o > 0; o >>= 1) s += __shfl_xor_sync(0xffffffffu, s, o);
    return s;
}

__device__ __forceinline__ float block_sum256(float v, float* sred) {
    __syncthreads();
    v = warp_sum(v);
    int warp = threadIdx.x >> 5, lane = threadIdx.x & 31;
    if (lane == 0) sred[warp] = v;
    __syncthreads();
    float t = 0.f;
#pragma unroll
    for (int w = 0; w < NWARP; w++) t += sred[w];
    return t;
}

// Grid barrier: all 148 blocks co-resident (1 CTA/SM).
__device__ __forceinline__ void grid_barrier() {
    __syncthreads();
    if (threadIdx.x == 0) {
        __threadfence();
        volatile unsigned* genp = &g_gen;
        unsigned gen = *genp;
        if (atomicAdd(&g_count, 1u) == GRID - 1) {
            atomicExch(&g_count, 0u);
            __threadfence();
            atomicExch(&g_gen, gen + 1u);
        } else {
            while (*genp == gen) { __nanosleep(20); }
            __threadfence();
        }
    }
    __syncthreads();
}

// One instruction prefetches a 4KB row to L2: lane i touches line at +i*128B.
__device__ __forceinline__ void prefetch_row4k(const float* p, int lane) {
    asm volatile("prefetch.global.L2 [%0];" :: "l"(p + lane * 32));
}

__device__ __forceinline__ void ln_block(const float* __restrict__ gvec,
                                         const float* __restrict__ w,
                                         const float* __restrict__ b,
                                         float* sred, float out[4]) {
    int t = threadIdx.x;
    float4 xv = __ldcg((const float4*)gvec + t);
    float mu = block_sum256(xv.x + xv.y + xv.z + xv.w, sred) * (1.f / D);
    float xa[4]; *(float4*)xa = xv;
    float da[4], vs = 0.f;
#pragma unroll
    for (int c = 0; c < 4; c++) { da[c] = xa[c] - mu; vs += da[c] * da[c]; }
    float var = block_sum256(vs, sred) * (1.f / D);
    float rstd = rsqrtf(var + 1e-5f);
    float wa[4], ba[4];
    *(float4*)wa = ((const float4*)w)[t];
    *(float4*)ba = ((const float4*)b)[t];
#pragma unroll
    for (int c = 0; c < 4; c++) out[c] = da[c] * rstd * wa[c] + ba[c];
}

__device__ __forceinline__ float dot8g(const float4* __restrict__ w4,
                                       const float4* __restrict__ v4, int lane) {
    float s = 0.f;
#pragma unroll
    for (int j = 0; j < 8; j++) {
        float4 a = w4[lane + 32 * j];
        float4 b = v4[lane + 32 * j];
        s = fmaf(a.x, b.x, s); s = fmaf(a.y, b.y, s);
        s = fmaf(a.z, b.z, s); s = fmaf(a.w, b.w, s);
    }
    return s;
}

__device__ __forceinline__ float dot8p(const float4* pre,
                                       const float4* __restrict__ v4, int lane) {
    float s = 0.f;
#pragma unroll
    for (int j = 0; j < 8; j++) {
        float4 b = v4[lane + 32 * j];
        s = fmaf(pre[j].x, b.x, s); s = fmaf(pre[j].y, b.y, s);
        s = fmaf(pre[j].z, b.z, s); s = fmaf(pre[j].w, b.w, s);
    }
    return s;
}

__global__ __launch_bounds__(NTH, 1) void rwkv_fused(
    const int* __restrict__ token, const float* __restrict__ state,
    const float* __restrict__ emb,
    const float* __restrict__ ln0_w, const float* __restrict__ ln0_b,
    const float* __restrict__ ln1_w, const float* __restrict__ ln1_b,
    const float* __restrict__ ln2_w, const float* __restrict__ ln2_b,
    const float* __restrict__ kw, const float* __restrict__ vw,
    const float* __restrict__ rw, const float* __restrict__ ow,
    const float* __restrict__ mk, const float* __restrict__ mv,
    const float* __restrict__ mr,
    const float* __restrict__ tf, const float* __restrict__ td,
    const float* __restrict__ fkw, const float* __restrict__ fvw,
    const float* __restrict__ frw,
    const float* __restrict__ fmk, const float* __restrict__ fmr,
    const float* __restrict__ lnw, const float* __restrict__ lnb,
    const float* __restrict__ head,
    float* __restrict__ logits, float* __restrict__ state_out) {
    __shared__ float sred[NWARP];
    __shared__ float s_buf[HD];   // 16KB, reused per phase

    const int t = threadIdx.x, warp = t >> 5, lane = t & 31, bid = blockIdx.x;
    const int wg = bid * NWARP + warp;          // 0..1183
    const bool act128 = (bid < 128);
    const int row = wg;                          // row for phases A/B/D

    // ---- embed: block 0 computes g_x = LN0(emb[token]) ----
    if (bid == 0) {
        float4 xv = ((const float4*)(emb + (size_t)token[0] * D))[t];
        float mu = block_sum256(xv.x + xv.y + xv.z + xv.w, sred) * (1.f / D);
        float dx = xv.x - mu, dy = xv.y - mu, dz = xv.z - mu, dw = xv.w - mu;
        float var = block_sum256(dx * dx + dy * dy + dz * dz + dw * dw, sred) * (1.f / D);
        float rstd = rsqrtf(var + 1e-5f);
        float4 wv = ((const float4*)ln0_w)[t];
        float4 bv = ((const float4*)ln0_b)[t];
        float4 o;
        o.x = dx * rstd * wv.x + bv.x;
        o.y = dy * rstd * wv.y + bv.y;
        o.z = dz * rstd * wv.z + bv.z;
        o.w = dw * rstd * wv.w + bv.w;
        ((float4*)g_x)[t] = o;
    }

    float4 pre[8];

    for (int l = 0; l < NL; l++) {
        const size_t lo = (size_t)l * D;
        const size_t sb = (size_t)l * 5 * D;

        // ================= Phase A: time mixing =================
        if (act128) {
            const float4* kr = (const float4*)(kw + lo * D + (size_t)row * D);
#pragma unroll
            for (int j = 0; j < 8; j++) pre[j] = kr[lane + 32 * j];
            // prefetch v/r rows to L2 — consumed right after the LN
            prefetch_row4k(vw + lo * D + (size_t)row * D, lane);
            prefetch_row4k(rw + lo * D + (size_t)row * D, lane);
        }
        grid_barrier();   // g_x final
        if (act128) {
            float xn4[4];
            ln_block(g_x, ln1_w + lo, ln1_b + lo, sred, xn4);
            float mka[4], mva[4], mra[4], sxa[4];
            *(float4*)mka = ((const float4*)(mk + lo))[t];
            *(float4*)mva = ((const float4*)(mv + lo))[t];
            *(float4*)mra = ((const float4*)(mr + lo))[t];
            *(float4*)sxa = ((const float4*)(state + sb + D))[t];  // sx_att
            int base = 4 * t;
#pragma unroll
            for (int c = 0; c < 4; c++) {
                float xn = xn4[c];
                s_buf[base + c]         = xn * mka[c] + sxa[c] * (1.f - mka[c]);
                s_buf[D + base + c]     = xn * mva[c] + sxa[c] * (1.f - mva[c]);
                s_buf[2 * D + base + c] = xn * mra[c] + sxa[c] * (1.f - mra[c]);
                if (bid == 0) state_out[sb + D + base + c] = xn;   // state row 1
            }
            __syncthreads();

            const float4* xk4 = (const float4*)s_buf;
            const float4* xv4 = (const float4*)(s_buf + D);
            const float4* xr4 = (const float4*)(s_buf + 2 * D);
            float sk = dot8p(pre, xk4, lane);
            float sv = dot8g((const float4*)(vw + lo * D + (size_t)row * D), xv4, lane);
            float sr = dot8g((const float4*)(rw + lo * D + (size_t)row * D), xr4, lane);
            sk = warp_sum(sk); sv = warp_sum(sv); sr = warp_sum(sr);

            if (lane == 0) {
                float aa = state[sb + 2 * D + row];
                float bb = state[sb + 3 * D + row];
                float pp = state[sb + 4 * D + row];
                float tfv = tf[lo + row];
                float tdv = td[lo + row];
                float k = sk, v = sv;
                float rs = 1.f / (1.f + expf(-sr));

                float ww = tfv + k;
                float qq = fmaxf(pp, ww);
                float e1 = expf(pp - qq);
                float e2 = expf(ww - qq);
                g_rwkv[row] = rs * (e1 * aa + e2 * v) / (e1 * bb + e2);

                float ww2 = pp + tdv;
                float qq2 = fmaxf(ww2, k);
                float e1b = expf(ww2 - qq2);
                float e2b = expf(k - qq2);
                state_out[sb + 2 * D + row] = e1b * aa + e2b * v;
                state_out[sb + 3 * D + row] = e1b * bb + e2b;
                state_out[sb + 4 * D + row] = qq2;
            }
        }

        // ================= Phase B: x += ow @ rwkv =================
        if (act128) {
            const float4* orow = (const float4*)(ow + lo * D + (size_t)row * D);
#pragma unroll
            for (int j = 0; j < 8; j++) pre[j] = orow[lane + 32 * j];
        }
        grid_barrier();   // g_rwkv complete
        if (act128) {
            ((float4*)s_buf)[t] = __ldcg((const float4*)g_rwkv + t);
            __syncthreads();
            float s = warp_sum(dot8p(pre, (const float4*)s_buf, lane));
            if (lane == 0) g_x[row] = __ldcg(g_x + row) + s;
        }

        // ================= Phase C: channel mix 1 =================
        // units: 0..HD-1 -> fkw rows, HD..HD+D-1 -> frw rows
        const int u1 = wg + TOTW;       // always < HD
        const int u2 = wg + 2 * TOTW;   // always < HD
        const int u3 = wg + 3 * TOTW;   // < HD+D always (4735 max)
        const int u4 = wg + 4 * TOTW;   // valid iff < HD+D  (wg < 384)
        {
            const float4* wr0 = (const float4*)(fkw + (size_t)l * HD * D + (size_t)wg * D);
#pragma unroll
            for (int j = 0; j < 8; j++) pre[j] = wr0[lane + 32 * j];
            // prefetch this warp's remaining units into L2 during barrier+LN
            const float* fk_base = fkw + (size_t)l * HD * D;
            prefetch_row4k(fk_base + (size_t)u1 * D, lane);
            prefetch_row4k(fk_base + (size_t)u2 * D, lane);
            prefetch_row4k((u3 < HD) ? fk_base + (size_t)u3 * D
                                     : frw + lo * D + (size_t)(u3 - HD) * D, lane);
            if (u4 < HD + D)
                prefetch_row4k(frw + lo * D + (size_t)(u4 - HD) * D, lane);
        }
        grid_barrier();   // g_x updated by phase B
        {
            float xn4[4];
            ln_block(g_x, ln2_w + lo, ln2_b + lo, sred, xn4);
            float mka[4], mra[4], sxa[4];
            *(float4*)mka = ((const float4*)(fmk + lo))[t];
            *(float4*)mra = ((const float4*)(fmr + lo))[t];
            *(float4*)sxa = ((const float4*)(state + sb))[t];      // sx_ffn
            int base = 4 * t;
#pragma unroll
            for (int c = 0; c < 4; c++) {
                float xn = xn4[c];
                s_buf[base + c]     = xn * mka[c] + sxa[c] * (1.f - mka[c]);
                s_buf[D + base + c] = xn * mra[c] + sxa[c] * (1.f - mra[c]);
                if (bid == 0) state_out[sb + base + c] = xn;       // state row 0
            }
            __syncthreads();

            const float4* xk4 = (const float4*)s_buf;
            const float4* xr4 = (const float4*)(s_buf + D);
            // peeled unit 0 (registers)
            {
                float s = warp_sum(dot8p(pre, xk4, lane));
                if (lane == 0) { float rl = fmaxf(s, 0.f); g_kk[wg] = rl * rl; }
            }
            // units u1,u2 (both fkw) — dual-issue for 2x MLP
            {
                const float* fk_base = fkw + (size_t)l * HD * D;
                const float4* r0 = (const float4*)(fk_base + (size_t)u1 * D);
                const float4* r1 = (const float4*)(fk_base + (size_t)u2 * D);
                float4 a0[8], a1[8];
#pragma unroll
                for (int j = 0; j < 8; j++) { a0[j] = r0[lane + 32 * j]; a1[j] = r1[lane + 32 * j]; }
                float s0 = 0.f, s1 = 0.f;
#pragma unroll
                for (int j = 0; j < 8; j++) {
                    float4 b = xk4[lane + 32 * j];
                    s0 = fmaf(a0[j].x, b.x, s0); s0 = fmaf(a0[j].y, b.y, s0);
                    s0 = fmaf(a0[j].z, b.z, s0); s0 = fmaf(a0[j].w, b.w, s0);
                    s1 = fmaf(a1[j].x, b.x, s1); s1 = fmaf(a1[j].y, b.y, s1);
                    s1 = fmaf(a1[j].z, b.z, s1); s1 = fmaf(a1[j].w, b.w, s1);
                }
                s0 = warp_sum(s0); s1 = warp_sum(s1);
                if (lane == 0) {
                    float rl0 = fmaxf(s0, 0.f); g_kk[u1] = rl0 * rl0;
                    float rl1 = fmaxf(s1, 0.f); g_kk[u2] = rl1 * rl1;
                }
            }
            // units u3 (mixed) and u4 (frw, conditional) — dual-issue
            {
                const float* fk_base = fkw + (size_t)l * HD * D;
                const float4* r0 = (u3 < HD)
                    ? (const float4*)(fk_base + (size_t)u3 * D)
                    : (const float4*)(frw + lo * D + (size_t)(u3 - HD) * D);
                const float4* x0 = (u3 < HD) ? xk4 : xr4;
                const bool has4 = (u4 < HD + D);
                const float4* r1 = has4
                    ? (const float4*)(frw + lo * D + (size_t)(u4 - HD) * D) : r0;
                float4 a0[8], a1[8];
#pragma unroll
                for (int j = 0; j < 8; j++) a0[j] = r0[lane + 32 * j];
                if (has4) {
#pragma unroll
                    for (int j = 0; j < 8; j++) a1[j] = r1[lane + 32 * j];
                }
                float s0 = 0.f, s1 = 0.f;
#pragma unroll
                for (int j = 0; j < 8; j++) {
                    float4 b = x0[lane + 32 * j];
                    s0 = fmaf(a0[j].x, b.x, s0); s0 = fmaf(a0[j].y, b.y, s0);
                    s0 = fmaf(a0[j].z, b.z, s0); s0 = fmaf(a0[j].w, b.w, s0);
                }
                if (has4) {
#pragma unroll
                    for (int j = 0; j < 8; j++) {
                        float4 b = xr4[lane + 32 * j];
                        s1 = fmaf(a1[j].x, b.x, s1); s1 = fmaf(a1[j].y, b.y, s1);
                        s1 = fmaf(a1[j].z, b.z, s1); s1 = fmaf(a1[j].w, b.w, s1);
                    }
                }
                s0 = warp_sum(s0);
                if (has4) s1 = warp_sum(s1);
                if (lane == 0) {
                    if (u3 < HD) { float rl = fmaxf(s0, 0.f); g_kk[u3] = rl * rl; }
                    else g_r2[u3 - HD] = 1.f / (1.f + expf(-s0));
                    if (has4) g_r2[u4 - HD] = 1.f / (1.f + expf(-s1));
                }
            }
        }

        // ================= Phase D: x += r2 * (fvw @ kk) =================
        if (act128) {
            const float* wrow = fvw + (size_t)l * D * HD + (size_t)row * HD;
            const float4* w4 = (const float4*)wrow;
#pragma unroll
            for (int j = 0; j < 8; j++) pre[j] = w4[lane + 32 * j];   // first 4KB
            // prefetch remaining 12KB of the row
            prefetch_row4k(wrow + 1024, lane);
            prefetch_row4k(wrow + 2048, lane);
            prefetch_row4k(wrow + 3072, lane);
        }
        grid_barrier();   // g_kk, g_r2 complete
        {
#pragma unroll
            for (int j = 0; j < 4; j++)
                ((float4*)s_buf)[t + NTH * j] = __ldcg((const float4*)g_kk + t + NTH * j);
            __syncthreads();
            if (act128) {
                const float4* k4 = (const float4*)s_buf;
                float s = dot8p(pre, k4, lane);  // chunk 0
                const float4* w4 = (const float4*)(fvw + (size_t)l * D * HD + (size_t)row * HD);
#pragma unroll
                for (int c = 1; c < 4; c++) {
                    float4 a[8];
#pragma unroll
                    for (int j = 0; j < 8; j++) a[j] = w4[c * 256 + lane + 32 * j];
#pragma unroll
                    for (int j = 0; j < 8; j++) {
                        float4 b = k4[c * 256 + lane + 32 * j];
                        s = fmaf(a[j].x, b.x, s); s = fmaf(a[j].y, b.y, s);
                        s = fmaf(a[j].z, b.z, s); s = fmaf(a[j].w, b.w, s);
                    }
                }
                s = warp_sum(s);
                if (lane == 0) g_x[row] = __ldcg(g_x + row) + __ldcg(g_r2 + row) * s;
            }
        }
    }

    // ================= Head: logits = head @ LN(x) =================
    {
        const float4* hr = (const float4*)(head + (size_t)wg * D);   // wg < NV
#pragma unroll
        for (int j = 0; j < 8; j++) pre[j] = hr[lane + 32 * j];
        prefetch_row4k(head + (size_t)(wg + TOTW) * D, lane);
        prefetch_row4k(head + (size_t)(wg + 2 * TOTW) * D, lane);
    }
    grid_barrier();   // g_x final
    {
        float xn4[4];
        ln_block(g_x, lnw, lnb, sred, xn4);
        int base = 4 * t;
#pragma unroll
        for (int c = 0; c < 4; c++) s_buf[base + c] = xn4[c];
        __syncthreads();

        const float4* x4 = (const float4*)s_buf;
        // peeled first row
        {
            float s = warp_sum(dot8p(pre, x4, lane));
            if (lane == 0) logits[wg] = s;
        }
        // two rows per iteration, prefetch one iteration ahead
        for (int v = wg + TOTW; v < NV; v += 2 * TOTW) {
            int v2 = v + TOTW;
            int p1 = v + 2 * TOTW, p2 = v + 3 * TOTW;
            if (p1 < NV) prefetch_row4k(head + (size_t)p1 * D, lane);
            if (p2 < NV) prefetch_row4k(head + (size_t)p2 * D, lane);
            if (v2 < NV) {
                const float4* r0 = (const float4*)(head + (size_t)v * D);
                const float4* r1 = (const float4*)(head + (size_t)v2 * D);
                float4 a0[8], a1[8];
#pragma unroll
                for (int j = 0; j < 8; j++) { a0[j] = r0[lane + 32 * j]; a1[j] = r1[lane + 32 * j]; }
                float s0 = 0.f, s1 = 0.f;
#pragma unroll
                for (int j = 0; j < 8; j++) {
                    float4 b = x4[lane + 32 * j];
                    s0 = fmaf(a0[j].x, b.x, s0); s0 = fmaf(a0[j].y, b.y, s0);
                    s0 = fmaf(a0[j].z, b.z, s0); s0 = fmaf(a0[j].w, b.w, s0);
                    s1 = fmaf(a1[j].x, b.x, s1); s1 = fmaf(a1[j].y, b.y, s1);
                    s1 = fmaf(a1[j].z, b.z, s1); s1 = fmaf(a1[j].w, b.w, s1);
                }
                s0 = warp_sum(s0); s1 = warp_sum(s1);
                if (lane == 0) { logits[v] = s0; logits[v2] = s1; }
            } else {
                const float4* r0 = (const float4*)(head + (size_t)v * D);
                float s0 = 0.f;
#pragma unroll
                for (int j = 0; j < 8; j++) {
                    float4 a = r0[lane + 32 * j];
                    float4 b = x4[lane + 32 * j];
                    s0 = fmaf(a.x, b.x, s0); s0 = fmaf(a.y, b.y, s0);
                    s0 = fmaf(a.z, b.z, s0); s0 = fmaf(a.w, b.w, s0);
                }
                s0 = warp_sum(s0);
                if (lane == 0) logits[v] = s0;
            }
        }
    }
}

// ---------------------------------------------------------------------------
extern "C" void kernel_launch(void* const* d_in, const int* in_sizes, int n_in,
                              void* d_out, int out_size) {
    const int*   token     = (const int*)d_in[0];
    const float* state     = (const float*)d_in[1];
    const float* emb       = (const float*)d_in[2];
    const float* ln0_w     = (const float*)d_in[3];
    const float* ln0_b     = (const float*)d_in[4];
    const float* ln1_w     = (const float*)d_in[5];
    const float* ln1_b     = (const float*)d_in[6];
    const float* ln2_w     = (const float*)d_in[7];
    const float* ln2_b     = (const float*)d_in[8];
    const float* att_key   = (const float*)d_in[9];
    const float* att_value = (const float*)d_in[10];
    const float* att_recep = (const float*)d_in[11];
    const float* att_out   = (const float*)d_in[12];
    const float* tm_k      = (const float*)d_in[13];
    const float* tm_v      = (const float*)d_in[14];
    const float* tm_r      = (const float*)d_in[15];
    const float* t_first   = (const float*)d_in[16];
    const float* t_decay   = (const float*)d_in[17];
    const float* ffn_key   = (const float*)d_in[18];
    const float* ffn_value = (const float*)d_in[19];
    const float* ffn_recep = (const float*)d_in[20];
    const float* ffn_tm_k  = (const float*)d_in[21];
    const float* ffn_tm_r  = (const float*)d_in[22];
    const float* lnout_w   = (const float*)d_in[23];
    const float* lnout_b   = (const float*)d_in[24];
    const float* head      = (const float*)d_in[25];

    float* out = (float*)d_out;
    float* logits = out;
    float* state_out;
    if (out_size >= NV + NL * 5 * D) {
        state_out = out + NV;
    } else {
        void* p = nullptr;
        cudaGetSymbolAddress(&p, g_state_scratch);
        state_out = (float*)p;
    }

    rwkv_fused<<<GRID, NTH>>>(token, state, emb, ln0_w, ln0_b,
                              ln1_w, ln1_b, ln2_w, ln2_b,
                              att_key, att_value, att_recep, att_out,
                              tm_k, tm_v, tm_r, t_first, t_decay,
                              ffn_key, ffn_value, ffn_recep,
                              ffn_tm_k, ffn_tm_r,
                              lnout_w, lnout_b, head,
                              logits, state_out);
}

// round 10
// speedup vs baseline: 1.3884x; 1.1716x over previous
#include <cuda_runtime.h>
#include <cuda_bf16.h>

// RWKV single-token inference, fp32 — persistent kernel (148x256).
// R10: cp.async (LDGSTS) double-buffered weight streaming into per-warp
// shared-memory staging; register-free MLP. Acq/rel grid barrier.
// D=1024, H=4096, L=24, V=50277.

#define D    1024
#define HD   4096
#define NL   24
#define NV   50277
#define GRID 148
#define NTH  256
#define NWARP 8
#define TOTW (GRID * NWARP)   // 1184 warps

// dynamic smem: [0,16KB) shared vector buffer, then 8 x 12KB warp staging
#define SBUF_F   4096                 // floats
#define WSLOT_F  1024                 // floats per 4KB slot
#define SMEM_DYN ((SBUF_F + NWARP * 3 * WSLOT_F) * 4)   // 114688 B

__device__ __align__(16) float g_x[D];
__device__ __align__(16) float g_rwkv[D];
__device__ __align__(16) float g_kk[HD];
__device__ __align__(16) float g_r2[D];
__device__ __align__(16) float g_state_scratch[NL * 5 * D];
__device__ unsigned g_count;
__device__ unsigned g_gen;

__device__ __forceinline__ float warp_sum(float s) {
#pragma unroll
    for (int o = 16; o > 0; o >>= 1) s += __shfl_xor_sync(0xffffffffu, s, o);
    return s;
}

__device__ __forceinline__ float block_sum256(float v, float* sred) {
    __syncthreads();
    v = warp_sum(v);
    int warp = threadIdx.x >> 5, lane = threadIdx.x & 31;
    if (lane == 0) sred[warp] = v;
    __syncthreads();
    float t = 0.f;
#pragma unroll
    for (int w = 0; w < NWARP; w++) t += sred[w];
    return t;
}

// Grid barrier, acq/rel atomics (all 148 blocks co-resident, 1 CTA/SM).
__device__ __forceinline__ void grid_barrier() {
    __syncthreads();
    if (threadIdx.x == 0) {
        unsigned gen;
        asm volatile("ld.global.relaxed.gpu.u32 %0, [%1];" : "=r"(gen) : "l"(&g_gen));
        unsigned old;
        asm volatile("atom.global.add.acq_rel.gpu.u32 %0, [%1], 1;"
                     : "=r"(old) : "l"(&g_count) : "memory");
        if (old == GRID - 1) {
            asm volatile("st.global.relaxed.gpu.u32 [%0], %1;" :: "l"(&g_count), "r"(0u) : "memory");
            asm volatile("st.global.release.gpu.u32 [%0], %1;" :: "l"(&g_gen), "r"(gen + 1u) : "memory");
        } else {
            unsigned cur;
            do {
                __nanosleep(20);
                asm volatile("ld.global.acquire.gpu.u32 %0, [%1];" : "=r"(cur) : "l"(&g_gen) : "memory");
            } while (cur == gen);
        }
    }
    __syncthreads();
}

// Issue one 4KB row (1024 floats) into shared via cp.async (per-lane 8x16B).
__device__ __forceinline__ void cpa_row(unsigned dst, const float* __restrict__ src, int lane) {
    unsigned d = dst + (unsigned)lane * 16u;
    const char* s = (const char*)src + lane * 16;
#pragma unroll
    for (int j = 0; j < 8; j++)
        asm volatile("cp.async.cg.shared.global [%0], [%1], 16;"
                     :: "r"(d + 512u * j), "l"(s + 512 * j) : "memory");
}
#define CPA_COMMIT() asm volatile("cp.async.commit_group;" ::: "memory")
#define CPA_WAIT(n)  asm volatile("cp.async.wait_group %0;" :: "n"(n) : "memory")

// dot of two 1024-float shared vectors (per-warp partial).
__device__ __forceinline__ float dot_ss(const float4* __restrict__ w4,
                                        const float4* __restrict__ v4, int lane) {
    float s = 0.f;
#pragma unroll
    for (int j = 0; j < 8; j++) {
        float4 a = w4[lane + 32 * j];
        float4 b = v4[lane + 32 * j];
        s = fmaf(a.x, b.x, s); s = fmaf(a.y, b.y, s);
        s = fmaf(a.z, b.z, s); s = fmaf(a.w, b.w, s);
    }
    return s;
}

// LayerNorm over g_x (L2-fresh via __ldcg); per-thread 4 outputs.
__device__ __forceinline__ void ln_block(const float* __restrict__ w,
                                         const float* __restrict__ b,
                                         float* sred, float out[4]) {
    int t = threadIdx.x;
    float4 xv = __ldcg((const float4*)g_x + t);
    float mu = block_sum256(xv.x + xv.y + xv.z + xv.w, sred) * (1.f / D);
    float xa[4]; *(float4*)xa = xv;
    float da[4], vs = 0.f;
#pragma unroll
    for (int c = 0; c < 4; c++) { da[c] = xa[c] - mu; vs += da[c] * da[c]; }
    float var = block_sum256(vs, sred) * (1.f / D);
    float rstd = rsqrtf(var + 1e-5f);
    float wa[4], ba[4];
    *(float4*)wa = ((const float4*)w)[t];
    *(float4*)ba = ((const float4*)b)[t];
#pragma unroll
    for (int c = 0; c < 4; c++) out[c] = da[c] * rstd * wa[c] + ba[c];
}

__global__ __launch_bounds__(NTH, 1) void rwkv_fused(
    const int* __restrict__ token, const float* __restrict__ state,
    const float* __restrict__ emb,
    const float* __restrict__ ln0_w, const float* __restrict__ ln0_b,
    const float* __restrict__ ln1_w, const float* __restrict__ ln1_b,
    const float* __restrict__ ln2_w, const float* __restrict__ ln2_b,
    const float* __restrict__ kw, const float* __restrict__ vw,
    const float* __restrict__ rw, const float* __restrict__ ow,
    const float* __restrict__ mk, const float* __restrict__ mv,
    const float* __restrict__ mr,
    const float* __restrict__ tf, const float* __restrict__ td,
    const float* __restrict__ fkw, const float* __restrict__ fvw,
    const float* __restrict__ frw,
    const float* __restrict__ fmk, const float* __restrict__ fmr,
    const float* __restrict__ lnw, const float* __restrict__ lnb,
    const float* __restrict__ head,
    float* __restrict__ logits, float* __restrict__ state_out) {
    __shared__ float sred[NWARP];
    extern __shared__ __align__(16) float dsm[];
    float* s_buf = dsm;                                   // 16KB shared vectors
    float* wbuf  = dsm + SBUF_F + (threadIdx.x >> 5) * (3 * WSLOT_F);  // 12KB/warp
    const unsigned wb_u32 = (unsigned)__cvta_generic_to_shared(wbuf);

    const int t = threadIdx.x, warp = t >> 5, lane = t & 31, bid = blockIdx.x;
    const int wg = bid * NWARP + warp;          // 0..1183
    const bool act128 = (bid < 128);
    const int row = wg;                          // row for phases A/B/D

    const float4* wb0 = (const float4*)wbuf;
    const float4* wb1 = (const float4*)(wbuf + WSLOT_F);
    const float4* wb2 = (const float4*)(wbuf + 2 * WSLOT_F);

    // ---- embed: block 0 computes g_x = LN0(emb[token]) ----
    if (bid == 0) {
        float4 xv = ((const float4*)(emb + (size_t)token[0] * D))[t];
        float mu = block_sum256(xv.x + xv.y + xv.z + xv.w, sred) * (1.f / D);
        float dx = xv.x - mu, dy = xv.y - mu, dz = xv.z - mu, dw = xv.w - mu;
        float var = block_sum256(dx * dx + dy * dy + dz * dz + dw * dw, sred) * (1.f / D);
        float rstd = rsqrtf(var + 1e-5f);
        float4 wv = ((const float4*)ln0_w)[t];
        float4 bv = ((const float4*)ln0_b)[t];
        float4 o;
        o.x = dx * rstd * wv.x + bv.x;
        o.y = dy * rstd * wv.y + bv.y;
        o.z = dz * rstd * wv.z + bv.z;
        o.w = dw * rstd * wv.w + bv.w;
        ((float4*)g_x)[t] = o;
    }

    for (int l = 0; l < NL; l++) {
        const size_t lo = (size_t)l * D;
        const size_t sb = (size_t)l * 5 * D;

        // ================= Phase A: time mixing =================
        if (act128) {
            cpa_row(wb_u32,            kw + lo * D + (size_t)row * D, lane);
            cpa_row(wb_u32 + 4096u,    vw + lo * D + (size_t)row * D, lane);
            cpa_row(wb_u32 + 8192u,    rw + lo * D + (size_t)row * D, lane);
            CPA_COMMIT();
        }
        grid_barrier();   // g_x final
        if (act128) {
            float xn4[4];
            ln_block(ln1_w + lo, ln1_b + lo, sred, xn4);
            float mka[4], mva[4], mra[4], sxa[4];
            *(float4*)mka = ((const float4*)(mk + lo))[t];
            *(float4*)mva = ((const float4*)(mv + lo))[t];
            *(float4*)mra = ((const float4*)(mr + lo))[t];
            *(float4*)sxa = ((const float4*)(state + sb + D))[t];  // sx_att
            int base = 4 * t;
#pragma unroll
            for (int c = 0; c < 4; c++) {
                float xn = xn4[c];
                s_buf[base + c]         = xn * mka[c] + sxa[c] * (1.f - mka[c]);
                s_buf[D + base + c]     = xn * mva[c] + sxa[c] * (1.f - mva[c]);
                s_buf[2 * D + base + c] = xn * mra[c] + sxa[c] * (1.f - mra[c]);
                if (bid == 0) state_out[sb + D + base + c] = xn;   // state row 1
            }
            __syncthreads();

            CPA_WAIT(0);
            float sk = warp_sum(dot_ss(wb0, (const float4*)s_buf, lane));
            float sv = warp_sum(dot_ss(wb1, (const float4*)(s_buf + D), lane));
            float sr = warp_sum(dot_ss(wb2, (const float4*)(s_buf + 2 * D), lane));

            if (lane == 0) {
                float aa = state[sb + 2 * D + row];
                float bb = state[sb + 3 * D + row];
                float pp = state[sb + 4 * D + row];
                float tfv = tf[lo + row];
                float tdv = td[lo + row];
                float k = sk, v = sv;
                float rs = 1.f / (1.f + expf(-sr));

                float ww = tfv + k;
                float qq = fmaxf(pp, ww);
                float e1 = expf(pp - qq);
                float e2 = expf(ww - qq);
                g_rwkv[row] = rs * (e1 * aa + e2 * v) / (e1 * bb + e2);

                float ww2 = pp + tdv;
                float qq2 = fmaxf(ww2, k);
                float e1b = expf(ww2 - qq2);
                float e2b = expf(k - qq2);
                state_out[sb + 2 * D + row] = e1b * aa + e2b * v;
                state_out[sb + 3 * D + row] = e1b * bb + e2b;
                state_out[sb + 4 * D + row] = qq2;
            }
        }

        // ================= Phase B: x += ow @ rwkv =================
        if (act128) {
            cpa_row(wb_u32, ow + lo * D + (size_t)row * D, lane);
            CPA_COMMIT();
        }
        grid_barrier();   // g_rwkv complete
        if (act128) {
            ((float4*)s_buf)[t] = __ldcg((const float4*)g_rwkv + t);
            __syncthreads();
            CPA_WAIT(0);
            float s = warp_sum(dot_ss(wb0, (const float4*)s_buf, lane));
            if (lane == 0) g_x[row] = __ldcg(g_x + row) + s;
        }

        // ================= Phase C: channel mix 1 =================
        // units: u<HD -> fkw row u (vs xk), else frw row u-HD (vs xr).
        const int u1 = wg + TOTW;        // < HD always
        const int u2 = wg + 2 * TOTW;    // < HD always
        const int u3 = wg + 3 * TOTW;    // < HD+D always; fkw iff wg < 544
        const int u4 = wg + 4 * TOTW;    // valid iff wg < 384; then frw
        const bool has5 = (u4 < HD + D);
        const float* fk_base = fkw + (size_t)l * HD * D;
        cpa_row(wb_u32,         fk_base + (size_t)wg * D, lane); CPA_COMMIT();
        cpa_row(wb_u32 + 4096u, fk_base + (size_t)u1 * D, lane); CPA_COMMIT();
        grid_barrier();   // g_x updated by phase B
        {
            float xn4[4];
            ln_block(ln2_w + lo, ln2_b + lo, sred, xn4);
            float mka[4], mra[4], sxa[4];
            *(float4*)mka = ((const float4*)(fmk + lo))[t];
            *(float4*)mra = ((const float4*)(fmr + lo))[t];
            *(float4*)sxa = ((const float4*)(state + sb))[t];      // sx_ffn
            int base = 4 * t;
#pragma unroll
            for (int c = 0; c < 4; c++) {
                float xn = xn4[c];
                s_buf[base + c]     = xn * mka[c] + sxa[c] * (1.f - mka[c]);
                s_buf[D + base + c] = xn * mra[c] + sxa[c] * (1.f - mra[c]);
                if (bid == 0) state_out[sb + base + c] = xn;       // state row 0
            }
            __syncthreads();

            const float4* xk4 = (const float4*)s_buf;
            const float4* xr4 = (const float4*)(s_buf + D);
            // u0
            CPA_WAIT(1);
            float s0 = warp_sum(dot_ss(wb0, xk4, lane));
            cpa_row(wb_u32, fk_base + (size_t)u2 * D, lane); CPA_COMMIT();
            if (lane == 0) { float rl = fmaxf(s0, 0.f); g_kk[wg] = rl * rl; }
            // u1
            CPA_WAIT(1);
            float s1 = warp_sum(dot_ss(wb1, xk4, lane));
            {
                const float* r3 = (u3 < HD) ? fk_base + (size_t)u3 * D
                                            : frw + lo * D + (size_t)(u3 - HD) * D;
                cpa_row(wb_u32 + 4096u, r3, lane); CPA_COMMIT();
            }
            if (lane == 0) { float rl = fmaxf(s1, 0.f); g_kk[u1] = rl * rl; }
            // u2
            CPA_WAIT(1);
            float s2 = warp_sum(dot_ss(wb0, xk4, lane));
            if (has5) { cpa_row(wb_u32, frw + lo * D + (size_t)(u4 - HD) * D, lane); CPA_COMMIT(); }
            if (lane == 0) { float rl = fmaxf(s2, 0.f); g_kk[u2] = rl * rl; }
            // u3
            if (has5) { CPA_WAIT(1); } else { CPA_WAIT(0); }
            {
                float s3 = warp_sum(dot_ss(wb1, (u3 < HD) ? xk4 : xr4, lane));
                if (lane == 0) {
                    if (u3 < HD) { float rl = fmaxf(s3, 0.f); g_kk[u3] = rl * rl; }
                    else g_r2[u3 - HD] = 1.f / (1.f + expf(-s3));
                }
            }
            // u4
            if (has5) {
                CPA_WAIT(0);
                float s4 = warp_sum(dot_ss(wb0, xr4, lane));
                if (lane == 0) g_r2[u4 - HD] = 1.f / (1.f + expf(-s4));
            }
        }

        // ================= Phase D: x += r2 * (fvw @ kk) =================
        const float* fv_row = fvw + (size_t)l * D * HD + (size_t)row * HD;
        if (act128) {
            cpa_row(wb_u32,         fv_row,        lane); CPA_COMMIT();
            cpa_row(wb_u32 + 4096u, fv_row + 1024, lane); CPA_COMMIT();
        }
        grid_barrier();   // g_kk, g_r2 complete
        {
#pragma unroll
            for (int j = 0; j < 4; j++)
                ((float4*)s_buf)[t + NTH * j] = __ldcg((const float4*)g_kk + t + NTH * j);
            __syncthreads();
            if (act128) {
                const float4* k4 = (const float4*)s_buf;
                CPA_WAIT(1);
                float s = dot_ss(wb0, k4, lane);
                cpa_row(wb_u32, fv_row + 2048, lane); CPA_COMMIT();
                CPA_WAIT(1);
                s += dot_ss(wb1, k4 + 256, lane);
                cpa_row(wb_u32 + 4096u, fv_row + 3072, lane); CPA_COMMIT();
                CPA_WAIT(1);
                s += dot_ss(wb0, k4 + 512, lane);
                CPA_WAIT(0);
                s += dot_ss(wb1, k4 + 768, lane);
                s = warp_sum(s);
                if (lane == 0) g_x[row] = __ldcg(g_x + row) + __ldcg(g_r2 + row) * s;
            }
        }
    }

    // ================= Head: logits = head @ LN(x) =================
    cpa_row(wb_u32,         head + (size_t)wg * D,            lane); CPA_COMMIT();
    cpa_row(wb_u32 + 4096u, head + (size_t)(wg + TOTW) * D,   lane); CPA_COMMIT();
    grid_barrier();   // g_x final
    {
        float xn4[4];
        ln_block(lnw, lnb, sred, xn4);
        int base = 4 * t;
#pragma unroll
        for (int c = 0; c < 4; c++) s_buf[base + c] = xn4[c];
        __syncthreads();

        const float4* x4 = (const float4*)s_buf;
        int i = 0;
        for (int v = wg; v < NV; v += TOTW, i++) {
            bool more = (v + 2 * TOTW) < NV;
            if (more) { CPA_WAIT(1); } else { CPA_WAIT(0); }
            const float4* wb = (i & 1) ? wb1 : wb0;
            float s = warp_sum(dot_ss(wb, x4, lane));
            if (more) {
                cpa_row(wb_u32 + ((i & 1) ? 4096u : 0u),
                        head + (size_t)(v + 2 * TOTW) * D, lane);
                CPA_COMMIT();
            }
            if (lane == 0) logits[v] = s;
        }
    }
}

// ---------------------------------------------------------------------------
extern "C" void kernel_launch(void* const* d_in, const int* in_sizes, int n_in,
                              void* d_out, int out_size) {
    const int*   token     = (const int*)d_in[0];
    const float* state     = (const float*)d_in[1];
    const float* emb       = (const float*)d_in[2];
    const float* ln0_w     = (const float*)d_in[3];
    const float* ln0_b     = (const float*)d_in[4];
    const float* ln1_w     = (const float*)d_in[5];
    const float* ln1_b     = (const float*)d_in[6];
    const float* ln2_w     = (const float*)d_in[7];
    const float* ln2_b     = (const float*)d_in[8];
    const float* att_key   = (const float*)d_in[9];
    const float* att_value = (const float*)d_in[10];
    const float* att_recep = (const float*)d_in[11];
    const float* att_out   = (const float*)d_in[12];
    const float* tm_k      = (const float*)d_in[13];
    const float* tm_v      = (const float*)d_in[14];
    const float* tm_r      = (const float*)d_in[15];
    const float* t_first   = (const float*)d_in[16];
    const float* t_decay   = (const float*)d_in[17];
    const float* ffn_key   = (const float*)d_in[18];
    const float* ffn_value = (const float*)d_in[19];
    const float* ffn_recep = (const float*)d_in[20];
    const float* ffn_tm_k  = (const float*)d_in[21];
    const float* ffn_tm_r  = (const float*)d_in[22];
    const float* lnout_w   = (const float*)d_in[23];
    const float* lnout_b   = (const float*)d_in[24];
    const float* head      = (const float*)d_in[25];

    float* out = (float*)d_out;
    float* logits = out;
    float* state_out;
    if (out_size >= NV + NL * 5 * D) {
        state_out = out + NV;
    } else {
        void* p = nullptr;
        cudaGetSymbolAddress(&p, g_state_scratch);
        state_out = (float*)p;
    }

    static bool attr_set = false;
    if (!attr_set) {
        cudaFuncSetAttribute(rwkv_fused, cudaFuncAttributeMaxDynamicSharedMemorySize,
                             SMEM_DYN);
        attr_set = true;
    }

    rwkv_fused<<<GRID, NTH, SMEM_DYN>>>(token, state, emb, ln0_w, ln0_b,
                                        ln1_w, ln1_b, ln2_w, ln2_b,
                                        att_key, att_value, att_recep, att_out,
                                        tm_k, tm_v, tm_r, t_first, t_decay,
                                        ffn_key, ffn_value, ffn_recep,
                                        ffn_tm_k, ffn_tm_r,
                                        lnout_w, lnout_b, head,
                                        logits, state_out);
}